// round 11
// baseline (speedup 1.0000x reference)
#include <cuda_runtime.h>
#include <cuda_bf16.h>
#include <math_constants.h>
#include <cstdint>
#include <cstddef>

// Problem constants
#define BATCH   8
#define SEQ     1024
#define DIM     512
#define HEADS   8
#define DHEAD   64
#define MROWS   (BATCH * SEQ)        // 8192
#define LOCALB  16

// Scratch (device globals; allocation is forbidden)
__device__ float g_q[MROWS * DIM];     // head-split [b][h][s][d]
__device__ float g_k[MROWS * DIM];
__device__ float g_v[MROWS * DIM];
__device__ float g_att[MROWS * DIM];   // merged-head [b][s][h*64+d]

__device__ __forceinline__ uint32_t f2tf32(float f) {
    uint32_t r;
    asm("cvt.rna.tf32.f32 %0, %1;" : "=r"(r) : "f"(f));
    return r;
}
__device__ __forceinline__ uint32_t smem_u32(const void* p) {
    uint32_t a;
    asm("{ .reg .u64 t; cvta.to.shared.u64 t, %1; cvt.u32.u64 %0, t; }" : "=r"(a) : "l"(p));
    return a;
}
__device__ __forceinline__ void cp_async16(uint32_t dst, const void* src) {
    asm volatile("cp.async.cg.shared.global [%0], [%1], 16;" :: "r"(dst), "l"(src));
}
#define CP_COMMIT() asm volatile("cp.async.commit_group;" ::: "memory")
#define CP_WAIT2()  asm volatile("cp.async.wait_group 2;" ::: "memory")

// ---------------------------------------------------------------------------
// tf32 tensor-core GEMM, cp.async 4-stage pipeline, RAW fp32 operands.
// tf32 RNA conversion applied in-register at fragment-load time.
// C[M,512] = A[M,512] @ W[512,512] + bias. 128x128 tile, BK=16,
// 8 warps x (64x32) of m16n8k8.
// ---------------------------------------------------------------------------
#define BK 16
#define APITCH 20
#define BPITCH 136
#define STAGES 4
#define AS_STRIDE (128 * APITCH)               // floats per A stage (2560)
#define BS_STRIDE (BK * BPITCH)                // floats per B stage (2176)
#define AS_BYTES  (STAGES * AS_STRIDE * 4)     // 40960
#define GEMM_SMEM ((STAGES * (AS_STRIDE + BS_STRIDE)) * 4)   // 75776

__device__ __forceinline__ void mma_tf32(
    float& c0, float& c1, float& c2, float& c3,
    uint32_t a0, uint32_t a1, uint32_t a2, uint32_t a3,
    uint32_t b0, uint32_t b1)
{
    asm volatile(
        "mma.sync.aligned.m16n8k8.row.col.f32.tf32.tf32.f32 "
        "{%0,%1,%2,%3}, {%4,%5,%6,%7}, {%8,%9}, {%0,%1,%2,%3};"
        : "+f"(c0), "+f"(c1), "+f"(c2), "+f"(c3)
        : "r"(a0), "r"(a1), "r"(a2), "r"(a3), "r"(b0), "r"(b1));
}

__device__ __forceinline__ void gemm_tf32_body(
    const float* __restrict__ A, const float* __restrict__ W,
    const float* __restrict__ bias, float* __restrict__ C,
    int headsplit, int bx, int by)
{
    extern __shared__ float dynsmem[];
    float* As = dynsmem;                          // [STAGES][128][APITCH]
    float* Bs = dynsmem + STAGES * AS_STRIDE;     // [STAGES][BK][BPITCH]
    const uint32_t sbase = smem_u32(dynsmem);

    const int tid  = threadIdx.x;
    const int warp = tid >> 5;
    const int lane = tid & 31;
    const int g    = lane >> 2;
    const int tig  = lane & 3;
    const int warp_m = warp >> 2;
    const int warp_n = warp & 3;

    const float* Aptr = A + (size_t)(by * 128) * DIM;
    const float* Wptr = W + bx * 128;

    const int arow = tid >> 2;             // 0..63 (+64)
    const int ac4  = (tid & 3) * 4;
    const int brow = tid >> 5;             // 0..7  (+8)
    const int bc4  = (tid & 31) * 4;

    // per-thread smem byte offsets (stage 0)
    const uint32_t a_d0 = sbase + (arow * APITCH + ac4) * 4;
    const uint32_t a_d1 = sbase + ((arow + 64) * APITCH + ac4) * 4;
    const uint32_t b_d0 = sbase + AS_BYTES + (brow * BPITCH + bc4) * 4;
    const uint32_t b_d1 = sbase + AS_BYTES + ((brow + 8) * BPITCH + bc4) * 4;

    float c[4][4][4];
#pragma unroll
    for (int i = 0; i < 4; i++)
#pragma unroll
        for (int j = 0; j < 4; j++)
#pragma unroll
            for (int r = 0; r < 4; r++) c[i][j][r] = 0.f;

    auto issue_stage = [&](int stage, int k0) {
        uint32_t ao = stage * (AS_STRIDE * 4);
        uint32_t bo = stage * (BS_STRIDE * 4);
        cp_async16(a_d0 + ao, Aptr + (size_t)arow * DIM + k0 + ac4);
        cp_async16(a_d1 + ao, Aptr + (size_t)(arow + 64) * DIM + k0 + ac4);
        cp_async16(b_d0 + bo, Wptr + (size_t)(k0 + brow) * DIM + bc4);
        cp_async16(b_d1 + bo, Wptr + (size_t)(k0 + brow + 8) * DIM + bc4);
    };

    const int NIT = DIM / BK;   // 32
    // prologue: stages 0..2
    issue_stage(0, 0);          CP_COMMIT();
    issue_stage(1, BK);         CP_COMMIT();
    issue_stage(2, 2 * BK);     CP_COMMIT();

    for (int it = 0; it < NIT; ++it) {
        CP_WAIT2();             // group 'it' complete (pending <= 2)
        __syncthreads();        // stage-it data visible; all warps past it-1

        const float* Ab = As + (it & 3) * AS_STRIDE;
        const float* Bb = Bs + (it & 3) * BS_STRIDE;
#pragma unroll
        for (int kk = 0; kk < 2; ++kk) {
            const int kb = kk * 8;
            uint32_t af[4][4];
#pragma unroll
            for (int mi = 0; mi < 4; mi++) {
                const int rb = warp_m * 64 + mi * 16;
                af[mi][0] = f2tf32(Ab[(rb + g) * APITCH + kb + tig]);
                af[mi][1] = f2tf32(Ab[(rb + g + 8) * APITCH + kb + tig]);
                af[mi][2] = f2tf32(Ab[(rb + g) * APITCH + kb + tig + 4]);
                af[mi][3] = f2tf32(Ab[(rb + g + 8) * APITCH + kb + tig + 4]);
            }
            uint32_t bf[4][2];
#pragma unroll
            for (int nj = 0; nj < 4; nj++) {
                const int cb = warp_n * 32 + nj * 8;
                bf[nj][0] = f2tf32(Bb[(kb + tig) * BPITCH + cb + g]);
                bf[nj][1] = f2tf32(Bb[(kb + tig + 4) * BPITCH + cb + g]);
            }
#pragma unroll
            for (int mi = 0; mi < 4; mi++)
#pragma unroll
                for (int nj = 0; nj < 4; nj++)
                    mma_tf32(c[mi][nj][0], c[mi][nj][1], c[mi][nj][2], c[mi][nj][3],
                             af[mi][0], af[mi][1], af[mi][2], af[mi][3],
                             bf[nj][0], bf[nj][1]);
        }

        // prefetch stage it+3 (writes buffer (it-1)&3 — safe past the barrier)
        if (it + 3 < NIT) issue_stage((it + 3) & 3, (it + 3) * BK);
        CP_COMMIT();            // empty commits at tail keep group count exact
    }

    // Epilogue
#pragma unroll
    for (int mi = 0; mi < 4; mi++) {
#pragma unroll
        for (int nj = 0; nj < 4; nj++) {
            const int cb = bx * 128 + warp_n * 32 + nj * 8 + tig * 2;
#pragma unroll
            for (int half = 0; half < 2; half++) {
                const int row = by * 128 + warp_m * 64 + mi * 16 + g + half * 8;
                float v0 = c[mi][nj][half * 2 + 0] + bias[cb];
                float v1 = c[mi][nj][half * 2 + 1] + bias[cb + 1];
                if (headsplit) {
                    int b = row >> 10, s = row & 1023;
                    int h = cb >> 6,  d = cb & 63;
                    size_t o = ((size_t)((b * HEADS + h) * SEQ + s) << 6) + d;
                    C[o]     = v0;
                    C[o + 1] = v1;
                } else {
                    C[(size_t)row * DIM + cb]     = v0;
                    C[(size_t)row * DIM + cb + 1] = v1;
                }
            }
        }
    }
}

__global__ __launch_bounds__(256, 2) void proj_qkv_kernel(
    const float* __restrict__ q,  const float* __restrict__ k,  const float* __restrict__ v,
    const float* __restrict__ Wq, const float* __restrict__ Wk, const float* __restrict__ Wv,
    const float* __restrict__ bq, const float* __restrict__ bk, const float* __restrict__ bv)
{
    const float* A; const float* W; const float* bias; float* C;
    if (blockIdx.z == 0)      { A = q; W = Wq; bias = bq; C = g_q; }
    else if (blockIdx.z == 1) { A = k; W = Wk; bias = bk; C = g_k; }
    else                      { A = v; W = Wv; bias = bv; C = g_v; }
    gemm_tf32_body(A, W, bias, C, 1, blockIdx.x, blockIdx.y);
}

__global__ __launch_bounds__(256, 2) void out_proj_kernel(
    const float* __restrict__ Wo, const float* __restrict__ bo, float* __restrict__ out)
{
    gemm_tf32_body(g_att, Wo, bo, out, 0, blockIdx.x, blockIdx.y);
}

// ---------------------------------------------------------------------------
// Sparse attention (R5 proven version, verbatim).
// ---------------------------------------------------------------------------
#define FULLMASK 0xffffffffu
#define AQ 32
#define BANDROWS (AQ + LOCALB)        // 48

__global__ __launch_bounds__(1024) void sparse_attn_kernel()
{
    __shared__ float Kb[BANDROWS][DHEAD];
    __shared__ float Vb[BANDROWS][DHEAD];

    const int warp = threadIdx.x >> 5;
    const int lane = threadIdx.x & 31;
    const int s0   = (blockIdx.x & (SEQ / AQ - 1)) * AQ;
    const int bh   = blockIdx.x / (SEQ / AQ);
    const int base = s0 - LOCALB;

    const float* Kp = g_k + (size_t)bh * SEQ * DHEAD;
    const float* Vp = g_v + (size_t)bh * SEQ * DHEAD;

    for (int task = threadIdx.x; task < BANDROWS * 16 * 2; task += 1024) {
        int which = task >= BANDROWS * 16;
        int tt    = which ? task - BANDROWS * 16 : task;
        int row   = tt >> 4;
        int c4    = (tt & 15) * 4;
        int j     = base + row;
        if (j >= 0) {
            const float* src = (which ? Vp : Kp) + ((size_t)j << 6) + c4;
            float4 val = *(const float4*)src;
            float* dst = which ? &Vb[row][c4] : &Kb[row][c4];
            *(float4*)dst = val;
        }
    }
    __syncthreads();

    const int s  = s0 + warp;
    const float* Qp = g_q + (size_t)bh * SEQ * DHEAD + ((size_t)s << 6);

    const float scale = 0.125f;
    float q0 = Qp[lane] * scale;
    float q1 = Qp[lane + 32] * scale;

    const float NEGINF = -CUDART_INF_F;
    float l0 = NEGINF, l1 = NEGINF;
    int   i0 = 0,      i1 = 0;
    int   count = 0;

    const int t = s >> 8;
    const int r = (s >> 4) & 15;

#define PROC_ROW(KRPTR, JIDX)                                                 \
    {                                                                         \
        const float* kr = (KRPTR);                                            \
        float p = q0 * kr[lane] + q1 * kr[lane + 32];                         \
        p += __shfl_xor_sync(FULLMASK, p, 16);                                \
        p += __shfl_xor_sync(FULLMASK, p, 8);                                 \
        p += __shfl_xor_sync(FULLMASK, p, 4);                                 \
        p += __shfl_xor_sync(FULLMASK, p, 2);                                 \
        p += __shfl_xor_sync(FULLMASK, p, 1);                                 \
        if (count < 32) { if (lane == count) { l0 = p; i0 = (JIDX); } }       \
        else            { if (lane == count - 32) { l1 = p; i1 = (JIDX); } }  \
        count++;                                                              \
    }

    const int dmax  = min(LOCALB, s);
    const int nBand = dmax + 1;
    for (int d = 0; d <= dmax; ++d) PROC_ROW(&Kb[warp + LOCALB - d][0], s - d);
    for (int m = 2; m <= r; ++m)    PROC_ROW(Kp + ((size_t)(s - 16 * m) << 6), s - 16 * m);
    for (int m = 1; m <= t; ++m)    PROC_ROW(Kp + ((size_t)(s - 256 * m) << 6), s - 256 * m);
#undef PROC_ROW

    float mx = fmaxf(l0, l1);
    mx = fmaxf(mx, __shfl_xor_sync(FULLMASK, mx, 16));
    mx = fmaxf(mx, __shfl_xor_sync(FULLMASK, mx, 8));
    mx = fmaxf(mx, __shfl_xor_sync(FULLMASK, mx, 4));
    mx = fmaxf(mx, __shfl_xor_sync(FULLMASK, mx, 2));
    mx = fmaxf(mx, __shfl_xor_sync(FULLMASK, mx, 1));

    float e0 = __expf(l0 - mx);
    float e1 = __expf(l1 - mx);
    float ssum = e0 + e1;
    ssum += __shfl_xor_sync(FULLMASK, ssum, 16);
    ssum += __shfl_xor_sync(FULLMASK, ssum, 8);
    ssum += __shfl_xor_sync(FULLMASK, ssum, 4);
    ssum += __shfl_xor_sync(FULLMASK, ssum, 2);
    ssum += __shfl_xor_sync(FULLMASK, ssum, 1);

    float acc0 = 0.f, acc1 = 0.f;
    for (int n = 0; n < nBand; ++n) {
        float p = __shfl_sync(FULLMASK, e0, n);
        const float* vr = &Vb[warp + LOCALB - n][0];
        acc0 = fmaf(p, vr[lane], acc0);
        acc1 = fmaf(p, vr[lane + 32], acc1);
    }
    for (int n = nBand; n < count; ++n) {
        float e = (n < 32) ? e0 : e1;
        int   jj = (n < 32) ? i0 : i1;
        float p = __shfl_sync(FULLMASK, e, n & 31);
        int   j = __shfl_sync(FULLMASK, jj, n & 31);
        const float* vr = Vp + ((size_t)j << 6);
        acc0 = fmaf(p, vr[lane], acc0);
        acc1 = fmaf(p, vr[lane + 32], acc1);
    }

    float inv = 1.0f / ssum;
    int b = bh >> 3, h = bh & 7;
    size_t o = ((size_t)(b * SEQ + s) * DIM) + h * DHEAD + lane;
    g_att[o]      = acc0 * inv;
    g_att[o + 32] = acc1 * inv;
}

// ---------------------------------------------------------------------------
extern "C" void kernel_launch(void* const* d_in, const int* in_sizes, int n_in,
                              void* d_out, int out_size)
{
    const float* query = (const float*)d_in[0];
    const float* key   = (const float*)d_in[1];
    const float* value = (const float*)d_in[2];
    const float* Wq    = (const float*)d_in[3];
    const float* bq    = (const float*)d_in[4];
    const float* Wk    = (const float*)d_in[5];
    const float* bk    = (const float*)d_in[6];
    const float* Wv    = (const float*)d_in[7];
    const float* bv    = (const float*)d_in[8];
    const float* Wo    = (const float*)d_in[9];
    const float* bo    = (const float*)d_in[10];
    float* out = (float*)d_out;

    cudaFuncSetAttribute(proj_qkv_kernel, cudaFuncAttributeMaxDynamicSharedMemorySize, GEMM_SMEM);
    cudaFuncSetAttribute(out_proj_kernel, cudaFuncAttributeMaxDynamicSharedMemorySize, GEMM_SMEM);

    dim3 blk(256);
    dim3 gridP(DIM / 128, MROWS / 128, 3);   // 4 x 64 x 3
    proj_qkv_kernel<<<gridP, blk, GEMM_SMEM>>>(query, key, value, Wq, Wk, Wv, bq, bk, bv);

    dim3 gridA(BATCH * HEADS * (SEQ / AQ));  // 2048 blocks, 1024 threads
    sparse_attn_kernel<<<gridA, dim3(1024)>>>();

    dim3 gridO(DIM / 128, MROWS / 128);      // 4 x 64
    out_proj_kernel<<<gridO, blk, GEMM_SMEM>>>(Wo, bo, out);
}

// round 12
// speedup vs baseline: 1.0566x; 1.0566x over previous
#include <cuda_runtime.h>
#include <cuda_bf16.h>
#include <math_constants.h>
#include <cstdint>
#include <cstddef>

// Problem constants
#define BATCH   8
#define SEQ     1024
#define DIM     512
#define HEADS   8
#define DHEAD   64
#define MROWS   (BATCH * SEQ)        // 8192
#define LOCALB  16

// Scratch (device globals; allocation is forbidden)
__device__ float g_q[MROWS * DIM];     // head-split [b][h][s][d]
__device__ float g_k[MROWS * DIM];
__device__ float g_v[MROWS * DIM];
__device__ float g_att[MROWS * DIM];   // merged-head, tf32-valued fp32
__device__ float g_wc[4 * DIM * DIM];  // tf32-converted Wq,Wk,Wv,Wo

__device__ __forceinline__ uint32_t f2tf32(float f) {
    uint32_t r;
    asm("cvt.rna.tf32.f32 %0, %1;" : "=r"(r) : "f"(f));
    return r;
}
__device__ __forceinline__ uint32_t smem_u32(const void* p) {
    uint32_t a;
    asm("{ .reg .u64 t; cvta.to.shared.u64 t, %1; cvt.u32.u64 %0, t; }" : "=r"(a) : "l"(p));
    return a;
}
__device__ __forceinline__ void cp_async16(uint32_t dst, const void* src) {
    asm volatile("cp.async.cg.shared.global [%0], [%1], 16;" :: "r"(dst), "l"(src));
}
#define CP_COMMIT() asm volatile("cp.async.commit_group;" ::: "memory")
#define CP_WAIT2()  asm volatile("cp.async.wait_group 2;" ::: "memory")

// ---------------------------------------------------------------------------
// Tiny pre-convert: only the 4 weight matrices (4 MB) -> RNA tf32.
// ---------------------------------------------------------------------------
#define W_F4 (DIM * DIM / 4)           // 65,536 float4 per weight

__global__ __launch_bounds__(256) void convert_w_kernel(
    const float4* __restrict__ Wq, const float4* __restrict__ Wk,
    const float4* __restrict__ Wv, const float4* __restrict__ Wo)
{
    int i = blockIdx.x * blockDim.x + threadIdx.x;
    if (i >= 4 * W_F4) return;
    int w   = i >> 16;                 // i / W_F4
    int off = i & (W_F4 - 1);
    const float4* src = (w == 0) ? Wq : (w == 1) ? Wk : (w == 2) ? Wv : Wo;
    float4 a = src[off];
    float4 t;
    t.x = __uint_as_float(f2tf32(a.x));
    t.y = __uint_as_float(f2tf32(a.y));
    t.z = __uint_as_float(f2tf32(a.z));
    t.w = __uint_as_float(f2tf32(a.w));
    ((float4*)(g_wc + (size_t)w * DIM * DIM))[off] = t;
}

// ---------------------------------------------------------------------------
// tf32 tensor-core GEMM, cp.async 4-stage pipeline.
// CVT_A=1: A operand is raw fp32, converted at fragment-load.
// CVT_A=0: A operand already tf32-valued. W always pre-converted (g_wc).
// 128x128 tile, BK=16, 8 warps x (64x32) of m16n8k8.
// ---------------------------------------------------------------------------
#define BK 16
#define APITCH 20
#define BPITCH 136
#define STAGES 4
#define AS_STRIDE (128 * APITCH)               // floats per A stage (2560)
#define BS_STRIDE (BK * BPITCH)                // floats per B stage (2176)
#define AS_BYTES  (STAGES * AS_STRIDE * 4)     // 40960
#define GEMM_SMEM ((STAGES * (AS_STRIDE + BS_STRIDE)) * 4)   // 75776

__device__ __forceinline__ void mma_tf32(
    float& c0, float& c1, float& c2, float& c3,
    uint32_t a0, uint32_t a1, uint32_t a2, uint32_t a3,
    uint32_t b0, uint32_t b1)
{
    asm volatile(
        "mma.sync.aligned.m16n8k8.row.col.f32.tf32.tf32.f32 "
        "{%0,%1,%2,%3}, {%4,%5,%6,%7}, {%8,%9}, {%0,%1,%2,%3};"
        : "+f"(c0), "+f"(c1), "+f"(c2), "+f"(c3)
        : "r"(a0), "r"(a1), "r"(a2), "r"(a3), "r"(b0), "r"(b1));
}

template <int CVT_A>
__device__ __forceinline__ void gemm_tf32_body(
    const float* __restrict__ A, const float* __restrict__ W,
    const float* __restrict__ bias, float* __restrict__ C,
    int headsplit, int bx, int by)
{
    extern __shared__ float dynsmem[];
    float* As = dynsmem;                          // [STAGES][128][APITCH]
    float* Bs = dynsmem + STAGES * AS_STRIDE;     // [STAGES][BK][BPITCH]
    const uint32_t sbase = smem_u32(dynsmem);

    const int tid  = threadIdx.x;
    const int warp = tid >> 5;
    const int lane = tid & 31;
    const int g    = lane >> 2;
    const int tig  = lane & 3;
    const int warp_m = warp >> 2;
    const int warp_n = warp & 3;

    const float* Aptr = A + (size_t)(by * 128) * DIM;
    const float* Wptr = W + bx * 128;

    const int arow = tid >> 2;             // 0..63 (+64)
    const int ac4  = (tid & 3) * 4;
    const int brow = tid >> 5;             // 0..7  (+8)
    const int bc4  = (tid & 31) * 4;

    const uint32_t a_d0 = sbase + (arow * APITCH + ac4) * 4;
    const uint32_t a_d1 = sbase + ((arow + 64) * APITCH + ac4) * 4;
    const uint32_t b_d0 = sbase + AS_BYTES + (brow * BPITCH + bc4) * 4;
    const uint32_t b_d1 = sbase + AS_BYTES + ((brow + 8) * BPITCH + bc4) * 4;

    float c[4][4][4];
#pragma unroll
    for (int i = 0; i < 4; i++)
#pragma unroll
        for (int j = 0; j < 4; j++)
#pragma unroll
            for (int r = 0; r < 4; r++) c[i][j][r] = 0.f;

    auto issue_stage = [&](int stage, int k0) {
        uint32_t ao = stage * (AS_STRIDE * 4);
        uint32_t bo = stage * (BS_STRIDE * 4);
        cp_async16(a_d0 + ao, Aptr + (size_t)arow * DIM + k0 + ac4);
        cp_async16(a_d1 + ao, Aptr + (size_t)(arow + 64) * DIM + k0 + ac4);
        cp_async16(b_d0 + bo, Wptr + (size_t)(k0 + brow) * DIM + bc4);
        cp_async16(b_d1 + bo, Wptr + (size_t)(k0 + brow + 8) * DIM + bc4);
    };

    const int NIT = DIM / BK;   // 32
    issue_stage(0, 0);          CP_COMMIT();
    issue_stage(1, BK);         CP_COMMIT();
    issue_stage(2, 2 * BK);     CP_COMMIT();

    for (int it = 0; it < NIT; ++it) {
        CP_WAIT2();
        __syncthreads();

        const float* Ab = As + (it & 3) * AS_STRIDE;
        const float* Bb = Bs + (it & 3) * BS_STRIDE;
#pragma unroll
        for (int kk = 0; kk < 2; ++kk) {
            const int kb = kk * 8;
            uint32_t af[4][4];
#pragma unroll
            for (int mi = 0; mi < 4; mi++) {
                const int rb = warp_m * 64 + mi * 16;
                float a0 = Ab[(rb + g) * APITCH + kb + tig];
                float a1 = Ab[(rb + g + 8) * APITCH + kb + tig];
                float a2 = Ab[(rb + g) * APITCH + kb + tig + 4];
                float a3 = Ab[(rb + g + 8) * APITCH + kb + tig + 4];
                if (CVT_A) {
                    af[mi][0] = f2tf32(a0); af[mi][1] = f2tf32(a1);
                    af[mi][2] = f2tf32(a2); af[mi][3] = f2tf32(a3);
                } else {
                    af[mi][0] = __float_as_uint(a0); af[mi][1] = __float_as_uint(a1);
                    af[mi][2] = __float_as_uint(a2); af[mi][3] = __float_as_uint(a3);
                }
            }
            uint32_t bf[4][2];
#pragma unroll
            for (int nj = 0; nj < 4; nj++) {
                const int cb = warp_n * 32 + nj * 8;
                bf[nj][0] = __float_as_uint(Bb[(kb + tig) * BPITCH + cb + g]);
                bf[nj][1] = __float_as_uint(Bb[(kb + tig + 4) * BPITCH + cb + g]);
            }
#pragma unroll
            for (int mi = 0; mi < 4; mi++)
#pragma unroll
                for (int nj = 0; nj < 4; nj++)
                    mma_tf32(c[mi][nj][0], c[mi][nj][1], c[mi][nj][2], c[mi][nj][3],
                             af[mi][0], af[mi][1], af[mi][2], af[mi][3],
                             bf[nj][0], bf[nj][1]);
        }

        if (it + 3 < NIT) issue_stage((it + 3) & 3, (it + 3) * BK);
        CP_COMMIT();
    }

    // Epilogue
#pragma unroll
    for (int mi = 0; mi < 4; mi++) {
#pragma unroll
        for (int nj = 0; nj < 4; nj++) {
            const int cb = bx * 128 + warp_n * 32 + nj * 8 + tig * 2;
#pragma unroll
            for (int half = 0; half < 2; half++) {
                const int row = by * 128 + warp_m * 64 + mi * 16 + g + half * 8;
                float v0 = c[mi][nj][half * 2 + 0] + bias[cb];
                float v1 = c[mi][nj][half * 2 + 1] + bias[cb + 1];
                if (headsplit) {
                    int b = row >> 10, s = row & 1023;
                    int h = cb >> 6,  d = cb & 63;
                    size_t o = ((size_t)((b * HEADS + h) * SEQ + s) << 6) + d;
                    C[o]     = v0;
                    C[o + 1] = v1;
                } else {
                    C[(size_t)row * DIM + cb]     = v0;
                    C[(size_t)row * DIM + cb + 1] = v1;
                }
            }
        }
    }
}

__global__ __launch_bounds__(256, 2) void proj_qkv_kernel(
    const float* __restrict__ q,  const float* __restrict__ k,  const float* __restrict__ v,
    const float* __restrict__ bq, const float* __restrict__ bk, const float* __restrict__ bv)
{
    const float* A; const float* W; const float* bias; float* C;
    if (blockIdx.z == 0)      { A = q; W = g_wc;                 bias = bq; C = g_q; }
    else if (blockIdx.z == 1) { A = k; W = g_wc + DIM * DIM;     bias = bk; C = g_k; }
    else                      { A = v; W = g_wc + 2 * DIM * DIM; bias = bv; C = g_v; }
    gemm_tf32_body<1>(A, W, bias, C, 1, blockIdx.x, blockIdx.y);
}

__global__ __launch_bounds__(256, 2) void out_proj_kernel(
    const float* __restrict__ bo, float* __restrict__ out)
{
    gemm_tf32_body<0>(g_att, g_wc + 3 * DIM * DIM, bo, out, 0, blockIdx.x, blockIdx.y);
}

// ---------------------------------------------------------------------------
// Sparse attention (R5 proven version; epilogue stores tf32-rounded values).
// ---------------------------------------------------------------------------
#define FULLMASK 0xffffffffu
#define AQ 32
#define BANDROWS (AQ + LOCALB)        // 48

__global__ __launch_bounds__(1024) void sparse_attn_kernel()
{
    __shared__ float Kb[BANDROWS][DHEAD];
    __shared__ float Vb[BANDROWS][DHEAD];

    const int warp = threadIdx.x >> 5;
    const int lane = threadIdx.x & 31;
    const int s0   = (blockIdx.x & (SEQ / AQ - 1)) * AQ;
    const int bh   = blockIdx.x / (SEQ / AQ);
    const int base = s0 - LOCALB;

    const float* Kp = g_k + (size_t)bh * SEQ * DHEAD;
    const float* Vp = g_v + (size_t)bh * SEQ * DHEAD;

    for (int task = threadIdx.x; task < BANDROWS * 16 * 2; task += 1024) {
        int which = task >= BANDROWS * 16;
        int tt    = which ? task - BANDROWS * 16 : task;
        int row   = tt >> 4;
        int c4    = (tt & 15) * 4;
        int j     = base + row;
        if (j >= 0) {
            const float* src = (which ? Vp : Kp) + ((size_t)j << 6) + c4;
            float4 val = *(const float4*)src;
            float* dst = which ? &Vb[row][c4] : &Kb[row][c4];
            *(float4*)dst = val;
        }
    }
    __syncthreads();

    const int s  = s0 + warp;
    const float* Qp = g_q + (size_t)bh * SEQ * DHEAD + ((size_t)s << 6);

    const float scale = 0.125f;
    float q0 = Qp[lane] * scale;
    float q1 = Qp[lane + 32] * scale;

    const float NEGINF = -CUDART_INF_F;
    float l0 = NEGINF, l1 = NEGINF;
    int   i0 = 0,      i1 = 0;
    int   count = 0;

    const int t = s >> 8;
    const int r = (s >> 4) & 15;

#define PROC_ROW(KRPTR, JIDX)                                                 \
    {                                                                         \
        const float* kr = (KRPTR);                                            \
        float p = q0 * kr[lane] + q1 * kr[lane + 32];                         \
        p += __shfl_xor_sync(FULLMASK, p, 16);                                \
        p += __shfl_xor_sync(FULLMASK, p, 8);                                 \
        p += __shfl_xor_sync(FULLMASK, p, 4);                                 \
        p += __shfl_xor_sync(FULLMASK, p, 2);                                 \
        p += __shfl_xor_sync(FULLMASK, p, 1);                                 \
        if (count < 32) { if (lane == count) { l0 = p; i0 = (JIDX); } }       \
        else            { if (lane == count - 32) { l1 = p; i1 = (JIDX); } }  \
        count++;                                                              \
    }

    const int dmax  = min(LOCALB, s);
    const int nBand = dmax + 1;
    for (int d = 0; d <= dmax; ++d) PROC_ROW(&Kb[warp + LOCALB - d][0], s - d);
    for (int m = 2; m <= r; ++m)    PROC_ROW(Kp + ((size_t)(s - 16 * m) << 6), s - 16 * m);
    for (int m = 1; m <= t; ++m)    PROC_ROW(Kp + ((size_t)(s - 256 * m) << 6), s - 256 * m);
#undef PROC_ROW

    float mx = fmaxf(l0, l1);
    mx = fmaxf(mx, __shfl_xor_sync(FULLMASK, mx, 16));
    mx = fmaxf(mx, __shfl_xor_sync(FULLMASK, mx, 8));
    mx = fmaxf(mx, __shfl_xor_sync(FULLMASK, mx, 4));
    mx = fmaxf(mx, __shfl_xor_sync(FULLMASK, mx, 2));
    mx = fmaxf(mx, __shfl_xor_sync(FULLMASK, mx, 1));

    float e0 = __expf(l0 - mx);
    float e1 = __expf(l1 - mx);
    float ssum = e0 + e1;
    ssum += __shfl_xor_sync(FULLMASK, ssum, 16);
    ssum += __shfl_xor_sync(FULLMASK, ssum, 8);
    ssum += __shfl_xor_sync(FULLMASK, ssum, 4);
    ssum += __shfl_xor_sync(FULLMASK, ssum, 2);
    ssum += __shfl_xor_sync(FULLMASK, ssum, 1);

    float acc0 = 0.f, acc1 = 0.f;
    for (int n = 0; n < nBand; ++n) {
        float p = __shfl_sync(FULLMASK, e0, n);
        const float* vr = &Vb[warp + LOCALB - n][0];
        acc0 = fmaf(p, vr[lane], acc0);
        acc1 = fmaf(p, vr[lane + 32], acc1);
    }
    for (int n = nBand; n < count; ++n) {
        float e = (n < 32) ? e0 : e1;
        int   jj = (n < 32) ? i0 : i1;
        float p = __shfl_sync(FULLMASK, e, n & 31);
        int   j = __shfl_sync(FULLMASK, jj, n & 31);
        const float* vr = Vp + ((size_t)j << 6);
        acc0 = fmaf(p, vr[lane], acc0);
        acc1 = fmaf(p, vr[lane + 32], acc1);
    }

    float inv = 1.0f / ssum;
    int b = bh >> 3, h = bh & 7;
    size_t o = ((size_t)(b * SEQ + s) * DIM) + h * DHEAD + lane;
    g_att[o]      = __uint_as_float(f2tf32(acc0 * inv));
    g_att[o + 32] = __uint_as_float(f2tf32(acc1 * inv));
}

// ---------------------------------------------------------------------------
extern "C" void kernel_launch(void* const* d_in, const int* in_sizes, int n_in,
                              void* d_out, int out_size)
{
    const float* query = (const float*)d_in[0];
    const float* key   = (const float*)d_in[1];
    const float* value = (const float*)d_in[2];
    const float* Wq    = (const float*)d_in[3];
    const float* bq    = (const float*)d_in[4];
    const float* Wk    = (const float*)d_in[5];
    const float* bk    = (const float*)d_in[6];
    const float* Wv    = (const float*)d_in[7];
    const float* bv    = (const float*)d_in[8];
    const float* Wo    = (const float*)d_in[9];
    const float* bo    = (const float*)d_in[10];
    float* out = (float*)d_out;

    cudaFuncSetAttribute(proj_qkv_kernel, cudaFuncAttributeMaxDynamicSharedMemorySize, GEMM_SMEM);
    cudaFuncSetAttribute(out_proj_kernel, cudaFuncAttributeMaxDynamicSharedMemorySize, GEMM_SMEM);

    // 1) pre-convert weights only (4 MB)
    convert_w_kernel<<<(4 * W_F4 + 255) / 256, 256>>>(
        (const float4*)Wq, (const float4*)Wk, (const float4*)Wv, (const float4*)Wo);

    // 2) QKV projections (A cvt'd at fragment load, W pre-converted)
    dim3 blk(256);
    dim3 gridP(DIM / 128, MROWS / 128, 3);   // 4 x 64 x 3
    proj_qkv_kernel<<<gridP, blk, GEMM_SMEM>>>(query, key, value, bq, bk, bv);

    // 3) sparse attention (writes tf32-valued g_att)
    dim3 gridA(BATCH * HEADS * (SEQ / AQ));  // 2048 blocks, 1024 threads
    sparse_attn_kernel<<<gridA, dim3(1024)>>>();

    // 4) output projection (no cvts anywhere)
    dim3 gridO(DIM / 128, MROWS / 128);      // 4 x 64
    out_proj_kernel<<<gridO, blk, GEMM_SMEM>>>(bo, out);
}